// round 2
// baseline (speedup 1.0000x reference)
#include <cuda_runtime.h>
#include <cstdint>

// ---------------------------------------------------------------------------
// Problem: x_{k+1}[v] = relu( sum_d W_in[v,d] * x_k[src[v,d]] - demand[v] ),
// 32 iterations, then out = weights * x_32. B=4, N=100K, D=16 (12 valid).
//
// R1 showed the iteration kernel is L1tex-wavefront bound on scattered 4B
// gathers (43K wf/SM ~ 23us). R2: stage x in shared-memory chunks and gather
// via LDS; edges sorted by src per node so a cursor consumes each edge once.
// ---------------------------------------------------------------------------

#define MAXN    430000
#define MAXSLOT 16
#define CHUNK   50176          // floats per staged chunk = 200704 B dyn smem
#define TPB     1024
#define DPT     4              // max dst nodes per thread
#define MAXBLK  2048

__device__ float g_w[(size_t)MAXN * MAXSLOT];          // softmax weights [dst][slot]
__device__ int2  g_e[(size_t)MAXSLOT * MAXN];          // sorted valid edges, SoA [pos][dst]
__device__ int   g_cnt[MAXN];                          // valid edge count per dst
__device__ int   g_lo[MAXBLK];                         // per iter-block min src
__device__ int   g_hi[MAXBLK];                         // per iter-block max src
__device__ __align__(16) float g_xa[MAXN];
__device__ __align__(16) float g_xb[MAXN];

// --- K1: masked softmax over D slots (thread per node) ---------------------
__global__ void k_softmax(const float* __restrict__ fp, const int* __restrict__ adj,
                          const int* __restrict__ num_nodes, int BN, int D) {
    int t = blockIdx.x * blockDim.x + threadIdx.x;
    if (t >= BN) return;
    const int N = __ldg(num_nodes);
    const float* f = fp + (size_t)t * D;
    const int*   a = adj + (size_t)t * D;

    float m = -3.402823466e38f;
    for (int d = 0; d < D; ++d) {
        float v = __ldg(f + d);
        if (__ldg(a + d) == N) v -= 1e7f;
        m = fmaxf(m, v);
    }
    float s = 0.f;
    for (int d = 0; d < D; ++d) {
        float v = __ldg(f + d);
        if (__ldg(a + d) == N) v -= 1e7f;
        s += __expf(v - m);
    }
    float inv = 1.f / s;
    for (int d = 0; d < D; ++d) {
        float v = __ldg(f + d);
        if (__ldg(a + d) == N) v -= 1e7f;
        g_w[(size_t)t * D + d] = __expf(v - m) * inv;
    }
}

// --- K2: gather in-edge weights, drop w==0 (padded), sort by src ascending -
// flow[fb,fs,fslot] = W * x[fb,fs]  with  W = g_w[fb*N+fs, fslot].
__global__ void k_gather_sort(const int* __restrict__ ii, const int* __restrict__ num_nodes,
                              int BN, int D) {
    int t = blockIdx.x * blockDim.x + threadIdx.x;
    if (t >= BN) return;
    const int N = __ldg(num_nodes);

    int   ssrc[MAXSLOT];
    float sw[MAXSLOT];
    int m = 0;
    for (int s = 0; s < D; ++s) {
        const int* r = ii + ((size_t)t * D + s) * 3;
        int fb = __ldg(r + 0);
        int fs = __ldg(r + 1);
        int fl = __ldg(r + 2);
        int src = fb * N + fs;
        float w = g_w[(size_t)src * D + fl];
        if (w != 0.0f) {
            int j = m++;
            while (j > 0 && ssrc[j - 1] > src) {
                ssrc[j] = ssrc[j - 1]; sw[j] = sw[j - 1]; --j;
            }
            ssrc[j] = src; sw[j] = w;
        }
    }
    g_cnt[t] = m;
    for (int j = 0; j < m; ++j)
        g_e[(size_t)j * BN + t] = make_int2(ssrc[j], __float_as_int(sw[j]));
}

// --- K3: per iter-block src range (edges sorted => min/max are endpoints) --
__global__ void k_range(int BN, int spb) {
    int t = blockIdx.x * blockDim.x + threadIdx.x;
    if (t >= BN) return;
    int m = g_cnt[t];
    if (m == 0) return;
    int mn = g_e[0 * (size_t)BN + t].x;
    int mx = g_e[(size_t)(m - 1) * BN + t].x;
    int blk = t / spb;
    atomicMin(&g_lo[blk], mn);
    atomicMax(&g_hi[blk], mx);
}

// --- K4: one fixed-point iteration with smem chunk staging -----------------
__global__ void __launch_bounds__(TPB) k_iter2(const float* __restrict__ dem,
                                               const float* __restrict__ xo,
                                               float* __restrict__ xn,
                                               int BN, int spb) {
    extern __shared__ float xs[];
    int blk   = blockIdx.x;
    int start = blk * spb;
    int stop  = min(start + spb, BN);
    int lo = g_lo[blk], hi = g_hi[blk];

    int   dd[DPT];
    int   cur[DPT];
    int   cnt[DPT];
    float acc[DPT];
#pragma unroll
    for (int k = 0; k < DPT; ++k) {
        int d = start + threadIdx.x + k * TPB;
        dd[k]  = d;
        cnt[k] = (d < stop) ? g_cnt[d] : 0;
        cur[k] = 0;
        acc[k] = 0.f;
    }

    if (lo <= hi) {
        int c0 = lo / CHUNK, c1 = hi / CHUNK;
        for (int c = c0; c <= c1; ++c) {
            int base = c * CHUNK;
            int lim  = min(CHUNK, BN - base);
            // stage chunk: coalesced float4 + scalar tail
            int nv = lim >> 2;
            const float4* s4 = (const float4*)(xo + base);
            float4*       d4 = (float4*)xs;
            for (int i = threadIdx.x; i < nv; i += TPB) d4[i] = s4[i];
            for (int i = (nv << 2) + threadIdx.x; i < lim; i += TPB) xs[i] = xo[base + i];
            __syncthreads();

            int end = base + CHUNK;
#pragma unroll
            for (int k = 0; k < DPT; ++k) {
                int d  = dd[k];
                int cu = cur[k], cn = cnt[k];
                float a = acc[k];
                while (cu < cn) {
                    int2 e = g_e[(size_t)cu * BN + d];
                    if (e.x >= end) break;
                    a = fmaf(__int_as_float(e.y), xs[e.x - base], a);
                    ++cu;
                }
                cur[k] = cu; acc[k] = a;
            }
            __syncthreads();
        }
    }

#pragma unroll
    for (int k = 0; k < DPT; ++k)
        if (dd[k] < stop)
            xn[dd[k]] = fmaxf(acc[k] - __ldg(dem + dd[k]), 0.f);
}

// --- K5: epilogue out[b,v,d] = weights[b,v,d] * x_final[b,v] ----------------
__global__ void k_final(float* __restrict__ out, const float* __restrict__ x,
                        int E, unsigned D) {
    int e = blockIdx.x * blockDim.x + threadIdx.x;
    if (e >= E) return;
    out[e] = g_w[e] * __ldg(x + (unsigned)e / D);
}

extern "C" void kernel_launch(void* const* d_in, const int* in_sizes, int n_in,
                              void* d_out, int out_size) {
    const float* fp  = (const float*)d_in[0];   // flow_proportions [B,N,D]
    const float* dem = (const float*)d_in[1];   // demands [B,N,1]
    const int*   adj = (const int*)d_in[2];     // adj_lst [B,N,D]
    const int*   ii  = (const int*)d_in[3];     // in_indices [B,N,D,3]
    const int*   nn  = (const int*)d_in[4];     // num_nodes scalar (device)

    const int E  = in_sizes[0];                 // B*N*D
    const int BN = in_sizes[1];                 // B*N
    const int D  = E / BN;

    void *pxa, *pxb, *plo, *phi;
    cudaGetSymbolAddress(&pxa, g_xa);
    cudaGetSymbolAddress(&pxb, g_xb);
    cudaGetSymbolAddress(&plo, g_lo);
    cudaGetSymbolAddress(&phi, g_hi);
    float* xa = (float*)pxa;
    float* xb = (float*)pxb;

    int sm = 148;
    cudaDeviceGetAttribute(&sm, cudaDevAttrMultiProcessorCount, 0);
    int grid = sm;
    int spb  = (BN + grid - 1) / grid;
    while (spb > DPT * TPB && grid < MAXBLK) {   // safety for bigger shapes
        grid *= 2;
        spb = (BN + grid - 1) / grid;
    }

    static int smem_set = 0;
    cudaFuncSetAttribute(k_iter2, cudaFuncAttributeMaxDynamicSharedMemorySize,
                         CHUNK * (int)sizeof(float));
    (void)smem_set;

    const int BT = 256;
    const int gN = (BN + BT - 1) / BT;
    const int gE = (E + BT - 1) / BT;

    k_softmax<<<gN, BT>>>(fp, adj, nn, BN, D);
    k_gather_sort<<<gN, BT>>>(ii, nn, BN, D);
    cudaMemsetAsync(plo, 0x7f, (size_t)grid * sizeof(int), 0);  // ~INT_MAX
    cudaMemsetAsync(phi, 0x00, (size_t)grid * sizeof(int), 0);
    k_range<<<gN, BT>>>(BN, spb);
    cudaMemsetAsync(xa, 0, (size_t)BN * sizeof(float), 0);

    for (int i = 0; i < 32; ++i) {
        const float* xo = (i & 1) ? xb : xa;
        float*       xn = (i & 1) ? xa : xb;
        k_iter2<<<grid, TPB, CHUNK * sizeof(float)>>>(dem, xo, xn, BN, spb);
    }
    // 32 iterations (even) => final x in xa
    k_final<<<gE, BT>>>((float*)d_out, xa, E, (unsigned)D);
}

// round 3
// speedup vs baseline: 2.2367x; 2.2367x over previous
#include <cuda_runtime.h>
#include <cstdint>

// ---------------------------------------------------------------------------
// x_{k+1}[v] = relu( sum_d W[v,d] * x_k[src[v,d]] - demand[v] ), 32 iters,
// out = weights * x_32.   B=4, N=100K, D=16 (12 valid).
//
// R1: scattered-LDG gather, L1tex-wavefront bound, 22.75us/iter.
// R2: smem staging + sorted cursor -> dependent-load chain, 60.8us/iter. BAD.
// R3: smem staging + predicated lockstep edge walk, batch-aligned chunks.
// ---------------------------------------------------------------------------

#define MAXN    430000
#define MAXSLOT 16
#define CHUNK   50176           // floats per staged chunk (200704 B dyn smem)
#define TPB     1024
#define DPT     4               // max dst nodes per thread

__device__ float g_w[(size_t)MAXN * MAXSLOT];   // softmax weights [dst][slot] (epilogue)
__device__ int2  g_e[(size_t)MAXSLOT * MAXN];   // compacted valid edges, SoA [pos][dst]
__device__ int   g_cnt[MAXN];                   // valid edge count per dst
__device__ __align__(16) float g_xa[MAXN];
__device__ __align__(16) float g_xb[MAXN];

// --- K1: masked softmax over D slots (thread per node) ---------------------
__global__ void k_softmax(const float* __restrict__ fp, const int* __restrict__ adj,
                          const int* __restrict__ num_nodes, int BN, int D) {
    int t = blockIdx.x * blockDim.x + threadIdx.x;
    if (t >= BN) return;
    const int N = __ldg(num_nodes);
    const float* f = fp + (size_t)t * D;
    const int*   a = adj + (size_t)t * D;

    float m = -3.402823466e38f;
    for (int d = 0; d < D; ++d) {
        float v = __ldg(f + d);
        if (__ldg(a + d) == N) v -= 1e7f;
        m = fmaxf(m, v);
    }
    float s = 0.f;
    for (int d = 0; d < D; ++d) {
        float v = __ldg(f + d);
        if (__ldg(a + d) == N) v -= 1e7f;
        s += __expf(v - m);
    }
    float inv = 1.f / s;
    for (int d = 0; d < D; ++d) {
        float v = __ldg(f + d);
        if (__ldg(a + d) == N) v -= 1e7f;
        g_w[(size_t)t * D + d] = __expf(v - m) * inv;
    }
}

// --- K2: gather in-edge weights, compact out padded (w==0) edges -----------
// flow[fb,fs,fslot] = W * x[fb*N+fs]  with  W = g_w[(fb*N+fs)*D + fslot].
__global__ void k_gather(const int* __restrict__ ii, const int* __restrict__ num_nodes,
                         int BN, int D) {
    int t = blockIdx.x * blockDim.x + threadIdx.x;
    if (t >= BN) return;
    const int N = __ldg(num_nodes);
    int m = 0;
    for (int s = 0; s < D; ++s) {
        const int* r = ii + ((size_t)t * D + s) * 3;
        int fb = __ldg(r + 0);
        int fs = __ldg(r + 1);
        int fl = __ldg(r + 2);
        int src = fb * N + fs;
        float w = g_w[(size_t)src * D + fl];
        if (w != 0.0f) {
            g_e[(size_t)m * BN + t] = make_int2(src, __float_as_int(w));
            ++m;
        }
    }
    g_cnt[t] = m;
}

// --- K3: one fixed-point iteration, smem-staged x, predicated edge walk ----
// Blocks are grouped per batch (bpb = gridDim.x / B); each block's dst range
// lies in one batch, so its sources span exactly ceil(N/CHUNK) chunks.
__global__ void __launch_bounds__(TPB, 1) k_iter3(const float* __restrict__ dem,
                                                  const float* __restrict__ xo,
                                                  float* __restrict__ xn,
                                                  int BN,
                                                  const int* __restrict__ num_nodes) {
    extern __shared__ float xs[];
    const int N   = __ldg(num_nodes);
    const int B   = BN / N;
    const int bpb = gridDim.x / B;           // blocks per batch
    const int blk = blockIdx.x;
    if (blk >= bpb * B) return;              // whole block exits: no sync hazard
    const int b     = blk / bpb;
    const int ib    = blk - b * bpb;
    const int spb   = (N + bpb - 1) / bpb;
    const int start = b * N + ib * spb;
    const int stop  = min(start + spb, (b + 1) * N);

    float acc[DPT];
    int   cnt[DPT];
#pragma unroll
    for (int k = 0; k < DPT; ++k) {
        int d  = start + threadIdx.x + k * TPB;
        cnt[k] = (d < stop) ? g_cnt[d] : 0;
        acc[k] = 0.f;
    }

    const int cb = (N + CHUNK - 1) / CHUNK;  // chunks per batch (2 for N=100K)
    for (int j = 0; j < cb; ++j) {
        const int base = b * N + j * CHUNK;
        const int lim  = min(CHUNK, N - j * CHUNK);

        // stage chunk of x into smem (coalesced float4 + tail)
        {
            const int nv = lim >> 2;
            const float4* s4 = (const float4*)(xo + base);
            float4*       d4 = (float4*)xs;
            for (int i = threadIdx.x; i < nv; i += TPB) d4[i] = s4[i];
            for (int i = (nv << 2) + threadIdx.x; i < lim; i += TPB) xs[i] = xo[base + i];
        }
        __syncthreads();

#pragma unroll
        for (int k = 0; k < DPT; ++k) {
            const int d = start + threadIdx.x + k * TPB;
            const int c = cnt[k];
            float a = acc[k];
#pragma unroll 4
            for (int pos = 0; pos < c; ++pos) {
                int2 e = g_e[(size_t)pos * BN + d];      // coalesced across warp
                unsigned off = (unsigned)(e.x - base);
                if (off < (unsigned)lim)
                    a = fmaf(__int_as_float(e.y), xs[off], a);
            }
            acc[k] = a;
        }
        __syncthreads();
    }

#pragma unroll
    for (int k = 0; k < DPT; ++k) {
        int d = start + threadIdx.x + k * TPB;
        if (d < stop)
            xn[d] = fmaxf(acc[k] - __ldg(dem + d), 0.f);
    }
}

// --- K4: epilogue out[b,v,d] = weights[b,v,d] * x_final[b,v] ----------------
__global__ void k_final(float* __restrict__ out, const float* __restrict__ x,
                        int E, unsigned D) {
    int e = blockIdx.x * blockDim.x + threadIdx.x;
    if (e >= E) return;
    out[e] = g_w[e] * __ldg(x + (unsigned)e / D);
}

extern "C" void kernel_launch(void* const* d_in, const int* in_sizes, int n_in,
                              void* d_out, int out_size) {
    const float* fp  = (const float*)d_in[0];   // flow_proportions [B,N,D]
    const float* dem = (const float*)d_in[1];   // demands [B,N,1]
    const int*   adj = (const int*)d_in[2];     // adj_lst [B,N,D]
    const int*   ii  = (const int*)d_in[3];     // in_indices [B,N,D,3]
    const int*   nn  = (const int*)d_in[4];     // num_nodes scalar (device)

    const int E  = in_sizes[0];                 // B*N*D
    const int BN = in_sizes[1];                 // B*N
    const int D  = E / BN;

    void *pxa, *pxb;
    cudaGetSymbolAddress(&pxa, g_xa);
    cudaGetSymbolAddress(&pxb, g_xb);
    float* xa = (float*)pxa;
    float* xb = (float*)pxb;

    int sm = 148;
    cudaDeviceGetAttribute(&sm, cudaDevAttrMultiProcessorCount, 0);
    const int grid = sm;                        // 152 on GB300; 152 % 4 == 0

    cudaFuncSetAttribute(k_iter3, cudaFuncAttributeMaxDynamicSharedMemorySize,
                         CHUNK * (int)sizeof(float));

    const int BT = 256;
    const int gN = (BN + BT - 1) / BT;
    const int gE = (E + BT - 1) / BT;

    k_softmax<<<gN, BT>>>(fp, adj, nn, BN, D);
    k_gather<<<gN, BT>>>(ii, nn, BN, D);
    cudaMemsetAsync(xa, 0, (size_t)BN * sizeof(float), 0);

    for (int i = 0; i < 32; ++i) {
        const float* xo = (i & 1) ? xb : xa;
        float*       xn = (i & 1) ? xa : xb;
        k_iter3<<<grid, TPB, CHUNK * sizeof(float)>>>(dem, xo, xn, BN, nn);
    }
    // 32 iterations (even) => final x in xa
    k_final<<<gE, BT>>>((float*)d_out, xa, E, (unsigned)D);
}

// round 4
// speedup vs baseline: 2.7747x; 1.2405x over previous
#include <cuda_runtime.h>
#include <cuda_fp16.h>
#include <cstdint>

// ---------------------------------------------------------------------------
// x_{k+1}[v] = relu( sum_d W[v,d]*x_k[src[v,d]] - demand[v] ), 32 iters,
// out = weights * x_32.  B=4, N=100K, D=16 (12 valid).
//
// R4: stage the WHOLE batch x (N halves = 200KB) in smem as fp16.
// Edge records carry the smem byte offset (src is intra-batch). 12 visits/dst,
// no chunk predication, one sync per iter. x stays fp32 in global.
// ---------------------------------------------------------------------------

#define MAXN       430000
#define MAXSLOT    16
#define TPB        1024
#define DPT        4
#define SMEM_BYTES 200704      // >= N*2 for N<=100352; dyn smem request

__device__ float g_w[(size_t)MAXN * MAXSLOT];   // softmax weights [dst][slot]
__device__ int2  g_e[(size_t)MAXSLOT * MAXN];   // edges SoA [pos][dst]: .x = smem byte off, .y = w bits
__device__ int   g_maxcnt;                      // max valid edges per dst
__device__ __align__(16) float g_xa[MAXN];
__device__ __align__(16) float g_xb[MAXN];

// --- K1: masked softmax over D slots (thread per node) ---------------------
__global__ void k_softmax(const float* __restrict__ fp, const int* __restrict__ adj,
                          const int* __restrict__ num_nodes, int BN, int D) {
    int t = blockIdx.x * blockDim.x + threadIdx.x;
    if (t >= BN) return;
    const int N = __ldg(num_nodes);
    const float* f = fp + (size_t)t * D;
    const int*   a = adj + (size_t)t * D;

    float m = -3.402823466e38f;
    for (int d = 0; d < D; ++d) {
        float v = __ldg(f + d);
        if (__ldg(a + d) == N) v -= 1e7f;
        m = fmaxf(m, v);
    }
    float s = 0.f;
    for (int d = 0; d < D; ++d) {
        float v = __ldg(f + d);
        if (__ldg(a + d) == N) v -= 1e7f;
        s += __expf(v - m);
    }
    float inv = 1.f / s;
    for (int d = 0; d < D; ++d) {
        float v = __ldg(f + d);
        if (__ldg(a + d) == N) v -= 1e7f;
        g_w[(size_t)t * D + d] = __expf(v - m) * inv;
    }
}

// --- K2: build edge records. off = fs*2 (intra-batch smem byte offset). ----
// Compact w!=0 to the front, pad remaining slots with (0, 0.0f) so the iter
// kernel can walk a uniform count with no predicate (w=0 * xs[0] == 0).
__global__ void k_gather(const int* __restrict__ ii, const int* __restrict__ num_nodes,
                         int BN, int D) {
    int t = blockIdx.x * blockDim.x + threadIdx.x;
    if (t >= BN) return;
    const int N = __ldg(num_nodes);
    int m = 0;
    for (int s = 0; s < D; ++s) {
        const int* r = ii + ((size_t)t * D + s) * 3;
        int fb = __ldg(r + 0);
        int fs = __ldg(r + 1);
        int fl = __ldg(r + 2);
        float w = g_w[((size_t)fb * N + fs) * D + fl];
        if (w != 0.0f) {
            g_e[(size_t)m * BN + t] = make_int2(fs * 2, __float_as_int(w));
            ++m;
        }
    }
    for (int s = m; s < D; ++s)
        g_e[(size_t)s * BN + t] = make_int2(0, 0);
    atomicMax(&g_maxcnt, m);   // uniform address -> ptxas REDUX aggregation
}

// --- K3: one iteration, whole-batch fp16 x in smem --------------------------
__global__ void __launch_bounds__(TPB, 1) k_iter4(const float* __restrict__ dem,
                                                  const float* __restrict__ xo,
                                                  float* __restrict__ xn,
                                                  int BN,
                                                  const int* __restrict__ num_nodes) {
    extern __shared__ unsigned char xs[];          // N halves
    const int N   = __ldg(num_nodes);
    const int B   = BN / N;
    const int bpb = gridDim.x / B;
    const int blk = blockIdx.x;
    if (blk >= bpb * B) return;                    // whole-block exit, pre-sync
    const int b     = blk / bpb;
    const int ib    = blk - b * bpb;
    const int spb   = (N + bpb - 1) / bpb;
    const int start = b * N + ib * spb;
    const int stop  = min(start + spb, (b + 1) * N);
    const int M     = g_maxcnt;

    const int cb = (N * 2 + SMEM_BYTES - 1) / SMEM_BYTES;   // chunks needed

    if (cb == 1) {
        // ---- stage whole batch x -> fp16 smem (vectorized when N%8==0) ----
        const float* xb0 = xo + b * N;
        if ((N & 7) == 0 && (((uintptr_t)xb0) & 15) == 0) {
            const float4* s4 = (const float4*)xb0;
            uint4* d4 = (uint4*)xs;
            int nv = N >> 3;
            for (int i = threadIdx.x; i < nv; i += TPB) {
                float4 f0 = __ldg(s4 + 2 * i);
                float4 f1 = __ldg(s4 + 2 * i + 1);
                uint4 o;
                __half2 h;
                h = __floats2half2_rn(f0.x, f0.y); o.x = *(unsigned*)&h;
                h = __floats2half2_rn(f0.z, f0.w); o.y = *(unsigned*)&h;
                h = __floats2half2_rn(f1.x, f1.y); o.z = *(unsigned*)&h;
                h = __floats2half2_rn(f1.z, f1.w); o.w = *(unsigned*)&h;
                d4[i] = o;
            }
        } else {
            __half* dh = (__half*)xs;
            for (int i = threadIdx.x; i < N; i += TPB)
                dh[i] = __float2half_rn(__ldg(xb0 + i));
        }
        __syncthreads();

        // ---- edge walk: M visits per dst, no predication -------------------
#pragma unroll
        for (int k = 0; k < DPT; ++k) {
            if (start + k * TPB >= stop) break;    // uniform across block
            int d  = start + threadIdx.x + k * TPB;
            int dl = min(d, stop - 1);             // clamp: safe duplicate read
            float a = 0.f;
#pragma unroll 4
            for (int pos = 0; pos < M; ++pos) {
                int2 e = g_e[pos * BN + dl];                      // coalesced
                __half h = *(const __half*)(xs + e.x);            // random LDS.U16
                a = fmaf(__half2float(h), __int_as_float(e.y), a);
            }
            if (d < stop)
                xn[d] = fmaxf(a - __ldg(dem + d), 0.f);
        }
    } else {
        // ---- fallback: chunked fp16 staging with range predicate ----------
        const int hpc = SMEM_BYTES / 2;            // halves per chunk
        float acc[DPT];
#pragma unroll
        for (int k = 0; k < DPT; ++k) acc[k] = 0.f;
        for (int j = 0; j < cb; ++j) {
            const int lo  = j * hpc;
            const int lim = min(hpc, N - lo);
            __half* dh = (__half*)xs;
            for (int i = threadIdx.x; i < lim; i += TPB)
                dh[i] = __float2half_rn(__ldg(xo + b * N + lo + i));
            __syncthreads();
            const unsigned base2 = (unsigned)lo * 2u, lim2 = (unsigned)lim * 2u;
#pragma unroll
            for (int k = 0; k < DPT; ++k) {
                if (start + k * TPB >= stop) break;
                int d  = start + threadIdx.x + k * TPB;
                int dl = min(d, stop - 1);
                float a = acc[k];
                for (int pos = 0; pos < M; ++pos) {
                    int2 e = g_e[pos * BN + dl];
                    unsigned rel = (unsigned)e.x - base2;
                    if (rel < lim2) {
                        __half h = *(const __half*)(xs + rel);
                        a = fmaf(__half2float(h), __int_as_float(e.y), a);
                    }
                }
                acc[k] = a;
            }
            __syncthreads();
        }
#pragma unroll
        for (int k = 0; k < DPT; ++k) {
            int d = start + threadIdx.x + k * TPB;
            if (d < stop)
                xn[d] = fmaxf(acc[k] - __ldg(dem + d), 0.f);
        }
    }
}

// --- K4: epilogue out[b,v,d] = weights[b,v,d] * x_final[b,v] ----------------
__global__ void k_final(float* __restrict__ out, const float* __restrict__ x,
                        int E, unsigned D) {
    int e = blockIdx.x * blockDim.x + threadIdx.x;
    if (e >= E) return;
    out[e] = g_w[e] * __ldg(x + (unsigned)e / D);
}

extern "C" void kernel_launch(void* const* d_in, const int* in_sizes, int n_in,
                              void* d_out, int out_size) {
    const float* fp  = (const float*)d_in[0];   // flow_proportions [B,N,D]
    const float* dem = (const float*)d_in[1];   // demands [B,N,1]
    const int*   adj = (const int*)d_in[2];     // adj_lst [B,N,D]
    const int*   ii  = (const int*)d_in[3];     // in_indices [B,N,D,3]
    const int*   nn  = (const int*)d_in[4];     // num_nodes scalar (device)

    const int E  = in_sizes[0];                 // B*N*D
    const int BN = in_sizes[1];                 // B*N
    const int D  = E / BN;

    void *pxa, *pxb, *pmc;
    cudaGetSymbolAddress(&pxa, g_xa);
    cudaGetSymbolAddress(&pxb, g_xb);
    cudaGetSymbolAddress(&pmc, g_maxcnt);
    float* xa = (float*)pxa;
    float* xb = (float*)pxb;

    int sm = 148;
    cudaDeviceGetAttribute(&sm, cudaDevAttrMultiProcessorCount, 0);
    const int grid = sm;                        // 152 on GB300 (divisible by B=4)

    cudaFuncSetAttribute(k_iter4, cudaFuncAttributeMaxDynamicSharedMemorySize,
                         SMEM_BYTES);

    const int BT = 256;
    const int gN = (BN + BT - 1) / BT;
    const int gE = (E + BT - 1) / BT;

    k_softmax<<<gN, BT>>>(fp, adj, nn, BN, D);
    cudaMemsetAsync(pmc, 0, sizeof(int), 0);
    k_gather<<<gN, BT>>>(ii, nn, BN, D);
    cudaMemsetAsync(xa, 0, (size_t)BN * sizeof(float), 0);

    for (int i = 0; i < 32; ++i) {
        const float* xo = (i & 1) ? xb : xa;
        float*       xn = (i & 1) ? xa : xb;
        k_iter4<<<grid, TPB, SMEM_BYTES>>>(dem, xo, xn, BN, nn);
    }
    // 32 iterations (even) => final x in xa
    k_final<<<gE, BT>>>((float*)d_out, xa, E, (unsigned)D);
}

// round 5
// speedup vs baseline: 3.7164x; 1.3394x over previous
#include <cuda_runtime.h>
#include <cuda_fp16.h>
#include <cstdint>

// ---------------------------------------------------------------------------
// x_{k+1}[v] = relu( sum_d W[v,d]*x_k[src[v,d]] - demand[v] ), 32 iters,
// out = weights * x_32.  B=4, N=100K, D=16 (12 valid).
//
// R5: x lives in GLOBAL fp16; staging = one cp.async.bulk (TMA) of the whole
// batch (200KB) into smem; edge walk in register groups of 4; epilogue fused
// into the last iteration (fp32 accumulator -> out), so output precision is
// identical to R4.
// ---------------------------------------------------------------------------

#define MAXN       430000
#define MAXSLOT    16
#define TPB        1024
#define DPT        4
#define SMEM_BYTES 200704      // dyn smem for staged fp16 x (N*2 <= this)

__device__ float g_w[(size_t)MAXN * MAXSLOT];   // softmax weights [dst][slot]
__device__ int2  g_e[(size_t)MAXSLOT * MAXN];   // edges SoA [pos][dst]: .x=smem byte off, .y=w bits
__device__ int   g_maxcnt;                      // max valid edges per dst
__device__ __align__(16) __half g_xa[MAXN];
__device__ __align__(16) __half g_xb[MAXN];

__device__ __forceinline__ unsigned smem_u32(const void* p) {
    unsigned r;
    asm("{ .reg .u64 t; cvta.to.shared.u64 t, %1; cvt.u32.u64 %0, t; }"
        : "=r"(r) : "l"(p));
    return r;
}

// --- K1: masked softmax over D slots (thread per node) ---------------------
__global__ void k_softmax(const float* __restrict__ fp, const int* __restrict__ adj,
                          const int* __restrict__ num_nodes, int BN, int D) {
    int t = blockIdx.x * blockDim.x + threadIdx.x;
    if (t >= BN) return;
    const int N = __ldg(num_nodes);
    const float* f = fp + (size_t)t * D;
    const int*   a = adj + (size_t)t * D;

    float m = -3.402823466e38f;
    for (int d = 0; d < D; ++d) {
        float v = __ldg(f + d);
        if (__ldg(a + d) == N) v -= 1e7f;
        m = fmaxf(m, v);
    }
    float s = 0.f;
    for (int d = 0; d < D; ++d) {
        float v = __ldg(f + d);
        if (__ldg(a + d) == N) v -= 1e7f;
        s += __expf(v - m);
    }
    float inv = 1.f / s;
    for (int d = 0; d < D; ++d) {
        float v = __ldg(f + d);
        if (__ldg(a + d) == N) v -= 1e7f;
        g_w[(size_t)t * D + d] = __expf(v - m) * inv;
    }
}

// --- K2: edge records: .x = intra-batch smem byte offset (fs*2), .y = w ----
// Compact w!=0 first; pad the rest with (0, 0.0f) so a fixed multiple-of-4
// walk is always safe (0-weight * xs[0] == 0).
__global__ void k_gather(const int* __restrict__ ii, const int* __restrict__ num_nodes,
                         int BN, int D) {
    int t = blockIdx.x * blockDim.x + threadIdx.x;
    if (t >= BN) return;
    const int N = __ldg(num_nodes);
    int m = 0;
    for (int s = 0; s < D; ++s) {
        const int* r = ii + ((size_t)t * D + s) * 3;
        int fb = __ldg(r + 0);
        int fs = __ldg(r + 1);
        int fl = __ldg(r + 2);
        float w = g_w[((size_t)fb * N + fs) * D + fl];
        if (w != 0.0f) {
            g_e[(size_t)m * BN + t] = make_int2(fs * 2, __float_as_int(w));
            ++m;
        }
    }
    for (int s = m; s < D; ++s)
        g_e[(size_t)s * BN + t] = make_int2(0, 0);
    atomicMax(&g_maxcnt, m);
}

// --- K3: one iteration. out!=nullptr on the LAST iteration => fused epilogue.
__global__ void __launch_bounds__(TPB, 1) k_iter5(const float* __restrict__ dem,
                                                  const __half* __restrict__ xo,
                                                  __half* __restrict__ xn,
                                                  float* __restrict__ out,
                                                  int BN, int D,
                                                  const int* __restrict__ num_nodes) {
    extern __shared__ unsigned char xs[];          // N fp16 values (staged x)
    __shared__ __align__(8) unsigned long long mbar;

    const int N   = __ldg(num_nodes);
    const int B   = BN / N;
    const int bpb = gridDim.x / B;
    const int blk = blockIdx.x;
    if (blk >= bpb * B) return;                    // whole-block exit (pre-sync)
    const int b     = blk / bpb;
    const int ib    = blk - b * bpb;
    const int spb   = (N + bpb - 1) / bpb;
    const int start = b * N + ib * spb;
    const int stop  = min(start + spb, (b + 1) * N);
    const int M4    = (g_maxcnt + 3) & ~3;         // padded edge count (mult of 4)

    const unsigned bytes = (unsigned)N * 2u;
    const bool whole = (bytes <= SMEM_BYTES);
    const bool bulk_ok = whole && ((bytes & 15u) == 0u);

    const unsigned mb = smem_u32(&mbar);
    if (bulk_ok) {
        if (threadIdx.x == 0)
            asm volatile("mbarrier.init.shared.b64 [%0], %1;" :: "r"(mb), "r"(1) : "memory");
        __syncthreads();
        if (threadIdx.x == 0) {
            asm volatile("mbarrier.arrive.expect_tx.shared.b64 _, [%0], %1;"
                         :: "r"(mb), "r"(bytes) : "memory");
            asm volatile("cp.async.bulk.shared::cta.global.mbarrier::complete_tx::bytes "
                         "[%0], [%1], %2, [%3];"
                         :: "r"(smem_u32(xs)), "l"(xo + (size_t)b * N), "r"(bytes), "r"(mb)
                         : "memory");
        }
    }

    // prefetch demands while the bulk copy is in flight
    float dm[DPT];
#pragma unroll
    for (int k = 0; k < DPT; ++k) {
        int d = start + threadIdx.x + k * TPB;
        dm[k] = (d < stop) ? __ldg(dem + d) : 0.f;
    }

    float r_out[DPT];

    if (whole) {
        if (bulk_ok) {
            unsigned done;
            do {
                asm volatile("{ .reg .pred p; "
                             "mbarrier.try_wait.parity.acquire.cta.shared::cta.b64 p, [%1], %2, 0x989680; "
                             "selp.b32 %0, 1, 0, p; }"
                             : "=r"(done) : "r"(mb), "r"(0u) : "memory");
            } while (!done);
            __syncthreads();    // all threads past the copy before any LDS
        } else {
            __half* dh = (__half*)xs;
            for (int i = threadIdx.x; i < N; i += TPB)
                dh[i] = __ldg(xo + (size_t)b * N + i);
            __syncthreads();
        }

        // ---- edge walk: M4 visits per dst in register groups of 4 ----------
#pragma unroll
        for (int k = 0; k < DPT; ++k) {
            if (start + k * TPB >= stop) { r_out[k] = 0.f; continue; }
            const int d  = start + threadIdx.x + k * TPB;
            const int dl = min(d, stop - 1);
            const int2* ep = g_e + dl;
            float a = 0.f;
            int2 e0 = ep[0], e1 = ep[BN], e2 = ep[2 * BN], e3 = ep[3 * BN];
            for (int g = 4; g < M4; g += 4) {
                int2 f0 = ep[g * BN], f1 = ep[(g + 1) * BN],
                     f2 = ep[(g + 2) * BN], f3 = ep[(g + 3) * BN];
                a = fmaf(__half2float(*(const __half*)(xs + e0.x)), __int_as_float(e0.y), a);
                a = fmaf(__half2float(*(const __half*)(xs + e1.x)), __int_as_float(e1.y), a);
                a = fmaf(__half2float(*(const __half*)(xs + e2.x)), __int_as_float(e2.y), a);
                a = fmaf(__half2float(*(const __half*)(xs + e3.x)), __int_as_float(e3.y), a);
                e0 = f0; e1 = f1; e2 = f2; e3 = f3;
            }
            a = fmaf(__half2float(*(const __half*)(xs + e0.x)), __int_as_float(e0.y), a);
            a = fmaf(__half2float(*(const __half*)(xs + e1.x)), __int_as_float(e1.y), a);
            a = fmaf(__half2float(*(const __half*)(xs + e2.x)), __int_as_float(e2.y), a);
            a = fmaf(__half2float(*(const __half*)(xs + e3.x)), __int_as_float(e3.y), a);
            r_out[k] = fmaxf(a - dm[k], 0.f);
        }
    } else {
        // ---- chunked fallback (N too big for smem): predicated walk --------
        const int hpc = SMEM_BYTES / 2;
        float acc[DPT];
#pragma unroll
        for (int k = 0; k < DPT; ++k) acc[k] = 0.f;
        const int cb = (N + hpc - 1) / hpc;
        for (int j = 0; j < cb; ++j) {
            const int lo  = j * hpc;
            const int lim = min(hpc, N - lo);
            __half* dh = (__half*)xs;
            for (int i = threadIdx.x; i < lim; i += TPB)
                dh[i] = __ldg(xo + (size_t)b * N + lo + i);
            __syncthreads();
            const unsigned base2 = (unsigned)lo * 2u, lim2 = (unsigned)lim * 2u;
#pragma unroll
            for (int k = 0; k < DPT; ++k) {
                if (start + k * TPB >= stop) continue;
                int d  = start + threadIdx.x + k * TPB;
                int dl = min(d, stop - 1);
                float a = acc[k];
                for (int pos = 0; pos < M4; ++pos) {
                    int2 e = g_e[(size_t)pos * BN + dl];
                    unsigned rel = (unsigned)e.x - base2;
                    if (rel < lim2)
                        a = fmaf(__half2float(*(const __half*)(xs + rel)),
                                 __int_as_float(e.y), a);
                }
                acc[k] = a;
            }
            __syncthreads();
        }
#pragma unroll
        for (int k = 0; k < DPT; ++k)
            r_out[k] = fmaxf(acc[k] - dm[k], 0.f);
    }

    if (out == nullptr) {
        // normal iteration: write fp16 x
#pragma unroll
        for (int k = 0; k < DPT; ++k) {
            int d = start + threadIdx.x + k * TPB;
            if (d < stop) xn[d] = __float2half_rn(r_out[k]);
        }
    } else {
        // LAST iteration: fused epilogue out[d, :] = g_w[d, :] * r  (fp32 r)
        __syncthreads();                         // done reading xs as fp16 x
        float* rs = (float*)xs;                  // reuse smem for r values
#pragma unroll
        for (int k = 0; k < DPT; ++k) {
            int d = start + threadIdx.x + k * TPB;
            if (d < stop) rs[d - start] = r_out[k];
        }
        __syncthreads();
        const int rows = stop - start;
        if ((D & 3) == 0) {
            const int dq = D >> 2;
            const int total4 = rows * dq;
            const float4* w4 = (const float4*)(g_w + (size_t)start * D);
            float4*       o4 = (float4*)(out + (size_t)start * D);
            for (int i = threadIdx.x; i < total4; i += TPB) {
                float4 w = __ldg(w4 + i);
                float  r = rs[i / dq];
                o4[i] = make_float4(w.x * r, w.y * r, w.z * r, w.w * r);
            }
        } else {
            const int total = rows * D;
            for (int i = threadIdx.x; i < total; i += TPB)
                out[(size_t)start * D + i] = g_w[(size_t)start * D + i] * rs[i / D];
        }
    }
}

extern "C" void kernel_launch(void* const* d_in, const int* in_sizes, int n_in,
                              void* d_out, int out_size) {
    const float* fp  = (const float*)d_in[0];   // flow_proportions [B,N,D]
    const float* dem = (const float*)d_in[1];   // demands [B,N,1]
    const int*   adj = (const int*)d_in[2];     // adj_lst [B,N,D]
    const int*   ii  = (const int*)d_in[3];     // in_indices [B,N,D,3]
    const int*   nn  = (const int*)d_in[4];     // num_nodes scalar (device)

    const int E  = in_sizes[0];                 // B*N*D
    const int BN = in_sizes[1];                 // B*N
    const int D  = E / BN;

    void *pxa, *pxb, *pmc;
    cudaGetSymbolAddress(&pxa, g_xa);
    cudaGetSymbolAddress(&pxb, g_xb);
    cudaGetSymbolAddress(&pmc, g_maxcnt);
    __half* xa = (__half*)pxa;
    __half* xb = (__half*)pxb;

    int sm = 148;
    cudaDeviceGetAttribute(&sm, cudaDevAttrMultiProcessorCount, 0);
    const int grid = sm;                        // 152 on GB300 (divisible by B=4)

    cudaFuncSetAttribute(k_iter5, cudaFuncAttributeMaxDynamicSharedMemorySize,
                         SMEM_BYTES);

    const int BT = 256;
    const int gN = (BN + BT - 1) / BT;

    k_softmax<<<gN, BT>>>(fp, adj, nn, BN, D);
    cudaMemsetAsync(pmc, 0, sizeof(int), 0);
    k_gather<<<gN, BT>>>(ii, nn, BN, D);
    cudaMemsetAsync(xa, 0, (size_t)BN * sizeof(__half), 0);

    for (int i = 0; i < 32; ++i) {
        const __half* xo = (i & 1) ? xb : xa;
        __half*       xn = (i & 1) ? xa : xb;
        float* out = (i == 31) ? (float*)d_out : nullptr;
        k_iter5<<<grid, TPB, SMEM_BYTES>>>(dem, xo, xn, out, BN, D, nn);
    }
}